// round 1
// baseline (speedup 1.0000x reference)
#include <cuda_runtime.h>

// ============================================================================
// FrequencyToSpatialCrossAttention — algebraically collapsed.
//
//  Qg = mean(X_f)                                     (k1: read 402MB)
//  A[b,h,c'] = scale * sum_d (Qg@Wq^T+bq)[h*48+d] * Wk[h*48+d,c']   (k2: tiny)
//  s[b,h,p]  = A[b,h,:] . X_s[b,:,p]    (bk const cancels in softmax)
//             stored at roll-shifted coords, windowed layout (k3: read 402MB)
//  w = softmax over 8x8 window, folded 1/nW            (k4: 17MB)
//  y[b,h,c]  = sum_p w[b,h,p] * X_s[b,c,p]             (k5: read 402MB)
//  out = ((Wv@y + bv per-head) @ Wo^T + bo), broadcast (k6 tiny, k7: write 402MB)
// ============================================================================

#define BATCH 4
#define CDIM  384
#define NH    8
#define HD    48
#define HWDIM 256
#define NPIX  65536      // 256*256
#define NWIN  1024       // 32*32 windows of 8x8

__device__ float g_S  [BATCH*NH*NPIX];   // scores -> weights (windowed layout), 8.4 MB
__device__ float g_Qg [BATCH*CDIM];
__device__ float g_A  [BATCH*CDIM*NH];   // layout [b][c][h], scale folded
__device__ float g_y  [BATCH*NH*CDIM];
__device__ float g_out[BATCH*CDIM];

// ---------------------------------------------------------------- k1: Qg mean
__global__ void k1_mean(const float* __restrict__ Xf) {
    int bc = blockIdx.x;                         // b*384+c
    const float4* src = (const float4*)Xf + (size_t)bc * 16384;
    float s = 0.f;
    for (int i = threadIdx.x; i < 16384; i += 256) {
        float4 v = src[i];
        s += (v.x + v.y) + (v.z + v.w);
    }
    __shared__ float red[256];
    red[threadIdx.x] = s;
    __syncthreads();
    for (int o = 128; o > 0; o >>= 1) {
        if (threadIdx.x < o) red[threadIdx.x] += red[threadIdx.x + o];
        __syncthreads();
    }
    if (threadIdx.x == 0) g_Qg[bc] = red[0] * (1.f / 65536.f);
}

// ------------------------------------------------- k2: Q proj + A, zero g_y
__global__ void k2_proj(const float* __restrict__ Wq, const float* __restrict__ bq,
                        const float* __restrict__ Wk) {
    int b = blockIdx.x, c = threadIdx.x;
    __shared__ float qf[CDIM];
    const float* qg = &g_Qg[b * CDIM];
    float acc = bq[c];
    for (int j = 0; j < CDIM; j++) acc += qg[j] * Wq[c * CDIM + j];
    qf[c] = acc;
    __syncthreads();
    const float scale = 0.14433756729740643f;   // 48^-0.5
    #pragma unroll
    for (int h = 0; h < NH; h++) {
        float a = 0.f;
        for (int d = 0; d < HD; d++) a += qf[h * HD + d] * Wk[(h * HD + d) * CDIM + c];
        g_A[(b * CDIM + c) * NH + h] = a * scale;
    }
    for (int i = threadIdx.x; i < NH * CDIM; i += CDIM) g_y[b * NH * CDIM + i] = 0.f;
}

// -------------------------------------------------------------- k3: scores
// 4 pixels/thread (float4), 8 head accumulators, A staged in smem [c][8h].
__global__ void __launch_bounds__(128) k3_scores(const float* __restrict__ Xs) {
    int b = blockIdx.x >> 7;
    int s = blockIdx.x & 127;
    int p0 = s * 512 + threadIdx.x * 4;

    __shared__ float sA[CDIM * NH];
    for (int i = threadIdx.x; i < CDIM * NH; i += 128) sA[i] = g_A[b * CDIM * NH + i];
    __syncthreads();

    const float4* xp = (const float4*)Xs + (size_t)b * CDIM * 16384 + (p0 >> 2);

    float4 acc[NH];
    #pragma unroll
    for (int h = 0; h < NH; h++) acc[h] = make_float4(0.f, 0.f, 0.f, 0.f);

    #pragma unroll 4
    for (int c = 0; c < CDIM; c++) {
        float4 xv = xp[(size_t)c * 16384];
        float4 a0 = *(const float4*)&sA[c * 8];
        float4 a1 = *(const float4*)&sA[c * 8 + 4];
        float av[8] = {a0.x, a0.y, a0.z, a0.w, a1.x, a1.y, a1.z, a1.w};
        #pragma unroll
        for (int h = 0; h < NH; h++) {
            acc[h].x += av[h] * xv.x;
            acc[h].y += av[h] * xv.y;
            acc[h].z += av[h] * xv.z;
            acc[h].w += av[h] * xv.w;
        }
    }

    // store at roll-shifted coords, windowed layout [b][h][win][64]
    int si = p0 >> 8, sj = p0 & 255;
    int ii = (si + 4) & 255, jj = (sj + 4) & 255;    // sj%4==0 -> jj group contiguous
    int win = (ii >> 3) * 32 + (jj >> 3);
    int inw = (ii & 7) * 8 + (jj & 7);               // multiple of 4
    #pragma unroll
    for (int h = 0; h < NH; h++) {
        int dst = ((b * 8 + h) * NWIN + win) * 64 + inw;
        *(float4*)&g_S[dst] = acc[h];
    }
}

// ------------------------------------------- k4: softmax per window (in-place)
// one warp per 64-score window; fold 1/nW into the weight.
__global__ void k4_softmax() {
    int gw   = blockIdx.x * 8 + (threadIdx.x >> 5);  // (b,h,win) flat
    int lane = threadIdx.x & 31;
    float* base = &g_S[gw * 64];
    float v0 = base[lane], v1 = base[lane + 32];
    float m = fmaxf(v0, v1);
    #pragma unroll
    for (int o = 16; o > 0; o >>= 1) m = fmaxf(m, __shfl_xor_sync(0xffffffffu, m, o));
    float e0 = expf(v0 - m), e1 = expf(v1 - m);
    float sum = e0 + e1;
    #pragma unroll
    for (int o = 16; o > 0; o >>= 1) sum += __shfl_xor_sync(0xffffffffu, sum, o);
    float inv = 1.f / (sum * 1024.f);                // 1/nW folded
    base[lane]      = e0 * inv;
    base[lane + 32] = e1 * inv;
}

// ---------------------------------------------------------------- k5: y accum
// y[b,h,c] = sum_p w[b,h,p]*x[b,c,p]. Smem-staged tall-skinny GEMM:
// block = (b, 64-channel chunk, 4096-pixel slice); 256 thr = 16 cg x 16 tg;
// register tile 4c x 8h; channel-interleaved (cg + i*16) rows, pitch 132
// floats -> conflict-free LDS.128. Tail: shfl over tg-pair + atomicAdd.
__global__ void __launch_bounds__(256) k5_y(const float* __restrict__ Xs) {
    int ps = blockIdx.x;        // 0..15
    int cchunk = blockIdx.y;    // 0..5
    int b = blockIdx.z;         // 0..3
    int cc0 = cchunk * 64;

    __shared__ float xt[64 * 132];
    __shared__ float wt[8 * 132];

    int tid = threadIdx.x;
    int cg = tid & 15, tg = tid >> 4;

    float acc[4][8];
    #pragma unroll
    for (int i = 0; i < 4; i++)
        #pragma unroll
        for (int h = 0; h < 8; h++) acc[i][h] = 0.f;

    int pbase0 = ps * 4096;
    const float4* xsp0 = (const float4*)Xs + (size_t)(b * CDIM + cc0) * 16384;

    for (int tile = 0; tile < 32; tile++) {
        int pbase = pbase0 + tile * 128;
        // x: 64ch x 128px
        #pragma unroll
        for (int j = 0; j < 8; j++) {
            int i = tid + j * 256;
            int c = i >> 5, tf4 = i & 31;
            float4 v = xsp0[(size_t)c * 16384 + (pbase >> 2) + tf4];
            *(float4*)&xt[c * 132 + tf4 * 4] = v;
        }
        // w: 8h x 128px (gather from windowed layout)
        {
            int h = tid >> 5, tf4 = tid & 31;
            int p = pbase + tf4 * 4;
            int si = p >> 8, sj = p & 255;
            int ii = (si + 4) & 255, jj = (sj + 4) & 255;
            int idx = ((b * 8 + h) * NWIN + (ii >> 3) * 32 + (jj >> 3)) * 64
                      + (ii & 7) * 8 + (jj & 7);
            *(float4*)&wt[h * 132 + tf4 * 4] = *(const float4*)&g_S[idx];
        }
        __syncthreads();

        #pragma unroll
        for (int u = 0; u < 2; u++) {
            int t4 = (tg * 2 + u) * 4;
            float4 wv[8];
            #pragma unroll
            for (int h = 0; h < 8; h++) wv[h] = *(const float4*)&wt[h * 132 + t4];
            #pragma unroll
            for (int i = 0; i < 4; i++) {
                float4 xv = *(const float4*)&xt[(cg + i * 16) * 132 + t4];
                #pragma unroll
                for (int h = 0; h < 8; h++)
                    acc[i][h] += xv.x * wv[h].x + xv.y * wv[h].y
                               + xv.z * wv[h].z + xv.w * wv[h].w;
            }
        }
        __syncthreads();
    }

    // combine the two tg's in this warp, then atomics from low half-warp
    #pragma unroll
    for (int i = 0; i < 4; i++)
        #pragma unroll
        for (int h = 0; h < 8; h++) {
            float v = acc[i][h] + __shfl_xor_sync(0xffffffffu, acc[i][h], 16);
            if ((tid & 31) < 16)
                atomicAdd(&g_y[b * NH * CDIM + h * CDIM + cc0 + cg + i * 16], v);
        }
}

// ----------------------------------------------------------- k6: tiny finals
__global__ void k6_out(const float* __restrict__ Wv, const float* __restrict__ bv,
                       const float* __restrict__ Wo, const float* __restrict__ bo) {
    int b = blockIdx.x, c = threadIdx.x;
    __shared__ float sy[NH * CDIM];
    __shared__ float pre[CDIM];
    for (int i = c; i < NH * CDIM; i += CDIM) sy[i] = g_y[b * NH * CDIM + i];
    __syncthreads();
    int h = c / HD;
    float a = bv[c];
    for (int j = 0; j < CDIM; j++) a += Wv[c * CDIM + j] * sy[h * CDIM + j];
    pre[c] = a;
    __syncthreads();
    float o = bo[c];
    for (int j = 0; j < CDIM; j++) o += Wo[c * CDIM + j] * pre[j];
    g_out[b * CDIM + c] = o;
}

// ------------------------------------------------------------- k7: broadcast
__global__ void k7_bcast(float* __restrict__ out) {
    int plane = blockIdx.x;                     // b*384+c
    int q = blockIdx.y;                         // quarter of the plane
    float v = g_out[plane];
    float4 vv = make_float4(v, v, v, v);
    float4* dst = (float4*)out + (size_t)plane * 16384 + q * 4096;
    for (int i = threadIdx.x; i < 4096; i += 256) dst[i] = vv;
}

// ============================================================================
extern "C" void kernel_launch(void* const* d_in, const int* in_sizes, int n_in,
                              void* d_out, int out_size) {
    const float* Xf = (const float*)d_in[0];
    const float* Xs = (const float*)d_in[1];
    const float* Wq = (const float*)d_in[2];
    const float* bq = (const float*)d_in[3];
    const float* Wk = (const float*)d_in[4];
    // d_in[5] = bk: per-(b,h) constant in scores, cancels in softmax -> unused
    const float* Wv = (const float*)d_in[6];
    const float* bv = (const float*)d_in[7];
    const float* Wo = (const float*)d_in[8];
    const float* bo = (const float*)d_in[9];

    k1_mean   <<<BATCH * CDIM, 256>>>(Xf);
    k2_proj   <<<BATCH, CDIM>>>(Wq, bq, Wk);
    k3_scores <<<BATCH * 128, 128>>>(Xs);
    k4_softmax<<<BATCH * NH * NWIN / 8, 256>>>();
    k5_y      <<<dim3(16, 6, BATCH), 256>>>(Xs);
    k6_out    <<<BATCH, CDIM>>>(Wv, bv, Wo, bo);
    k7_bcast  <<<dim3(BATCH * CDIM, 4), 256>>>((float*)d_out);
}

// round 3
// speedup vs baseline: 1.0011x; 1.0011x over previous
#include <cuda_runtime.h>

// ============================================================================
// FrequencyToSpatialCrossAttention — algebraically collapsed, FFMA2 edition.
//
//  Qg = mean(X_f)                                        (k1: read 402MB)
//  A[b,h,c'] = scale * q_h . Wk_h[:,c']                  (k2: tiny)
//  k3: per 8x64 strip (8 windows): scores (FFMA2) + in-block softmax
//      -> weights to g_S windowed layout                 (read 402MB)
//  k5: y[b,h,c] = sum_p w[b,h,p]*x[b,c,p]  (FFMA2, smem-staged, block-reduced)
//                                                        (read 402MB)
//  k6: out = (Wv@y+bv)@Wo^T+bo ; k7: broadcast           (write 402MB)
// ============================================================================

#define BATCH 4
#define CDIM  384
#define NH    8
#define NPIX  65536
#define NWIN  1024

typedef unsigned long long ull;

__device__ __forceinline__ ull pk(float x, float y) {
    ull r; asm("mov.b64 %0, {%1,%2};" : "=l"(r) : "f"(x), "f"(y)); return r;
}
__device__ __forceinline__ void upk(ull v, float& x, float& y) {
    asm("mov.b64 {%0,%1}, %2;" : "=f"(x), "=f"(y) : "l"(v));
}
__device__ __forceinline__ ull ffma2(ull a, ull b, ull c) {
    ull d; asm("fma.rn.f32x2 %0, %1, %2, %3;" : "=l"(d) : "l"(a), "l"(b), "l"(c));
    return d;
}

__device__ float g_S  [BATCH*NH*NPIX];   // softmaxed weights, windowed layout
__device__ float g_Qg [BATCH*CDIM];
__device__ float g_A  [BATCH*CDIM*NH];   // [b][c][h], scale folded
__device__ float g_y  [BATCH*NH*CDIM];
__device__ float g_out[BATCH*CDIM];

// ---------------------------------------------------------------- k1: Qg mean
// 512 threads; each iteration reads src[i] and src[i+512], stride 1024:
// covers 0..16383 exactly once (16 iters), max index 16383.
__global__ void k1_mean(const float* __restrict__ Xf) {
    int bc = blockIdx.x;
    const float4* src = (const float4*)Xf + (size_t)bc * 16384;
    float s0 = 0.f, s1 = 0.f;
    #pragma unroll 8
    for (int i = threadIdx.x; i < 16384; i += 1024) {
        float4 a = src[i], b = src[i + 512];
        s0 += (a.x + a.y) + (a.z + a.w);
        s1 += (b.x + b.y) + (b.z + b.w);
    }
    float s = s0 + s1;
    __shared__ float red[512];
    red[threadIdx.x] = s;
    __syncthreads();
    for (int o = 256; o > 0; o >>= 1) {
        if (threadIdx.x < o) red[threadIdx.x] += red[threadIdx.x + o];
        __syncthreads();
    }
    if (threadIdx.x == 0) g_Qg[bc] = red[0] * (1.f / 65536.f);
}

// ------------------------------------------------- k2: Q proj + A, zero g_y
__global__ void k2_proj(const float* __restrict__ Wq, const float* __restrict__ bq,
                        const float* __restrict__ Wk) {
    int b = blockIdx.x, c = threadIdx.x;
    __shared__ float qf[CDIM];
    const float* qg = &g_Qg[b * CDIM];
    float acc = bq[c];
    for (int j = 0; j < CDIM; j++) acc += qg[j] * Wq[c * CDIM + j];
    qf[c] = acc;
    __syncthreads();
    const float scale = 0.14433756729740643f;   // 48^-0.5
    #pragma unroll
    for (int h = 0; h < NH; h++) {
        float a = 0.f;
        for (int d = 0; d < 48; d++) a += qf[h * 48 + d] * Wk[(h * 48 + d) * CDIM + c];
        g_A[(b * CDIM + c) * NH + h] = a * scale;
    }
    for (int i = threadIdx.x; i < NH * CDIM; i += CDIM) g_y[b * NH * CDIM + i] = 0.f;
}

// ------------------------------------- k3: scores + softmax per 8x64 strip
// block = (b, window-row wr 0..31, strip st 0..3): 8 windows = 8 rows x 64 cols
// thread t: row r = t>>4, colgroup cg = t&15 -> 4 px (float4).
__global__ void __launch_bounds__(128) k3_scores(const float* __restrict__ Xs) {
    int bx = blockIdx.x;
    int b  = bx >> 7;
    int wr = (bx & 127) >> 2;
    int st = bx & 3;
    int t  = threadIdx.x;
    int r  = t >> 4, cg = t & 15;

    __shared__ ull   sA2[CDIM * NH];          // duplicated (a,a) pairs, 24KB
    __shared__ float sS[NH * 520];            // scores [h][512] pitch 520

    for (int i = t; i < CDIM * NH; i += 128) {
        float a = g_A[b * CDIM * NH + i];
        sA2[i] = pk(a, a);
    }
    __syncthreads();

    // shifted source coords (rolled[ii] = orig[ii-4 mod 256])
    int ii = wr * 8 + r;
    int jj = st * 64 + cg * 4;
    int si = (ii + 252) & 255;
    int sj = (jj + 252) & 255;
    const float4* xp = (const float4*)(Xs + (size_t)b * CDIM * NPIX
                                          + si * 256 + sj);

    ull acc[NH][2];
    #pragma unroll
    for (int h = 0; h < NH; h++) { acc[h][0] = pk(0.f, 0.f); acc[h][1] = pk(0.f, 0.f); }

    #pragma unroll 4
    for (int c = 0; c < CDIM; c++) {
        float4 xv = xp[(size_t)c * 16384];
        ull xlo = pk(xv.x, xv.y), xhi = pk(xv.z, xv.w);
        const ulonglong2* a4 = (const ulonglong2*)&sA2[c * 8];
        #pragma unroll
        for (int q = 0; q < 4; q++) {
            ulonglong2 ap = a4[q];
            acc[2*q  ][0] = ffma2(xlo, ap.x, acc[2*q  ][0]);
            acc[2*q  ][1] = ffma2(xhi, ap.x, acc[2*q  ][1]);
            acc[2*q+1][0] = ffma2(xlo, ap.y, acc[2*q+1][0]);
            acc[2*q+1][1] = ffma2(xhi, ap.y, acc[2*q+1][1]);
        }
    }

    int ploc = r * 64 + cg * 4;
    #pragma unroll
    for (int h = 0; h < NH; h++) {
        float a0, a1, a2, a3;
        upk(acc[h][0], a0, a1);
        upk(acc[h][1], a2, a3);
        *(float4*)&sS[h * 520 + ploc] = make_float4(a0, a1, a2, a3);
    }
    __syncthreads();

    // softmax: 64 (h,w) pairs, 2 threads per pair (sub = rows 0-3 / 4-7)
    int pair = t >> 1, sub = t & 1;
    int h = pair >> 3, w = pair & 7;
    int base = h * 520 + w * 8;
    float4 v[8];
    #pragma unroll
    for (int rr = 0; rr < 4; rr++) {
        int rowoff = base + (sub * 4 + rr) * 64;
        v[rr*2]   = *(const float4*)&sS[rowoff];
        v[rr*2+1] = *(const float4*)&sS[rowoff + 4];
    }
    float m = -1e30f;
    #pragma unroll
    for (int q = 0; q < 8; q++)
        m = fmaxf(m, fmaxf(fmaxf(v[q].x, v[q].y), fmaxf(v[q].z, v[q].w)));
    m = fmaxf(m, __shfl_xor_sync(0xffffffffu, m, 1));
    float Z = 0.f;
    #pragma unroll
    for (int q = 0; q < 8; q++) {
        v[q].x = __expf(v[q].x - m); v[q].y = __expf(v[q].y - m);
        v[q].z = __expf(v[q].z - m); v[q].w = __expf(v[q].w - m);
        Z += (v[q].x + v[q].y) + (v[q].z + v[q].w);
    }
    Z += __shfl_xor_sync(0xffffffffu, Z, 1);
    float inv = 1.f / (Z * 1024.f);             // fold 1/nW

    size_t gbase = ((size_t)(b * 8 + h) * NWIN + wr * 32 + st * 8 + w) * 64;
    #pragma unroll
    for (int rr = 0; rr < 4; rr++) {
        int rloc = (sub * 4 + rr) * 8;
        float4 e0 = v[rr*2], e1 = v[rr*2+1];
        e0.x *= inv; e0.y *= inv; e0.z *= inv; e0.w *= inv;
        e1.x *= inv; e1.y *= inv; e1.z *= inv; e1.w *= inv;
        *(float4*)&g_S[gbase + rloc]     = e0;
        *(float4*)&g_S[gbase + rloc + 4] = e1;
    }
}

// ---------------------------------------------------------------- k5: y accum
__global__ void __launch_bounds__(256) k5_y(const float* __restrict__ Xs) {
    int ps = blockIdx.x;        // 0..15 pixel slice (4096 px)
    int cchunk = blockIdx.y;    // 0..5
    int b = blockIdx.z;
    int cc0 = cchunk * 64;

    __shared__ float xt[64 * 132];
    __shared__ float wt[8 * 132];

    int tid = threadIdx.x;
    int cg = tid & 15, tg = tid >> 4;
    int lane = tid & 31, wid = tid >> 5;

    ull acc[4][8];
    #pragma unroll
    for (int i = 0; i < 4; i++)
        #pragma unroll
        for (int h = 0; h < 8; h++) acc[i][h] = pk(0.f, 0.f);

    int pbase0 = ps * 4096;
    const float4* xsp0 = (const float4*)Xs + (size_t)(b * CDIM + cc0) * 16384;

    for (int tile = 0; tile < 32; tile++) {
        int pbase = pbase0 + tile * 128;
        // stage x: 64ch x 128px
        #pragma unroll
        for (int j = 0; j < 8; j++) {
            int i = tid + j * 256;
            int c = i >> 5, tf4 = i & 31;
            float4 vx = xsp0[(size_t)c * 16384 + (pbase >> 2) + tf4];
            *(float4*)&xt[c * 132 + tf4 * 4] = vx;
        }
        // stage w: 8h x 128px from windowed layout
        {
            int h = tid >> 5, tf4 = tid & 31;
            int p = pbase + tf4 * 4;
            int sy = p >> 8, sx = p & 255;
            int iy = (sy + 4) & 255, ix = (sx + 4) & 255;
            size_t idx = ((size_t)(b * 8 + h) * NWIN + (iy >> 3) * 32 + (ix >> 3)) * 64
                         + (iy & 7) * 8 + (ix & 7);
            *(float4*)&wt[h * 132 + tf4 * 4] = *(const float4*)&g_S[idx];
        }
        __syncthreads();

        #pragma unroll
        for (int u = 0; u < 2; u++) {
            int t4 = (tg * 2 + u) * 4;
            ull wlo[8], whi[8];
            #pragma unroll
            for (int h = 0; h < 8; h++) {
                float4 wv = *(const float4*)&wt[h * 132 + t4];
                wlo[h] = pk(wv.x, wv.y); whi[h] = pk(wv.z, wv.w);
            }
            #pragma unroll
            for (int i = 0; i < 4; i++) {
                float4 xv = *(const float4*)&xt[(cg + i * 16) * 132 + t4];
                ull xlo = pk(xv.x, xv.y), xhi = pk(xv.z, xv.w);
                #pragma unroll
                for (int h = 0; h < 8; h++) {
                    acc[i][h] = ffma2(xlo, wlo[h], acc[i][h]);
                    acc[i][h] = ffma2(xhi, whi[h], acc[i][h]);
                }
            }
        }
        __syncthreads();
    }

    // fold: packed halves + tg-pair (shfl 16), stash per-warp partials in xt,
    // then one atomicAdd per (h,c) per block.
    float* sred = xt;   // reuse (synced above)
    #pragma unroll
    for (int i = 0; i < 4; i++)
        #pragma unroll
        for (int h = 0; h < 8; h++) {
            float lo, hi; upk(acc[i][h], lo, hi);
            float vsum = lo + hi;
            vsum += __shfl_xor_sync(0xffffffffu, vsum, 16);
            if (lane < 16) sred[wid * 512 + i * 128 + h * 16 + lane] = vsum;
        }
    __syncthreads();
    #pragma unroll
    for (int o = tid; o < 512; o += 256) {
        float s = 0.f;
        #pragma unroll
        for (int w = 0; w < 8; w++) s += sred[w * 512 + o];
        int i = o >> 7, h = (o >> 4) & 7, c = cc0 + (o & 15) + 16 * i;
        atomicAdd(&g_y[b * NH * CDIM + h * CDIM + c], s);
    }
}

// ----------------------------------------------------------- k6: tiny finals
__global__ void k6_out(const float* __restrict__ Wv, const float* __restrict__ bv,
                       const float* __restrict__ Wo, const float* __restrict__ bo) {
    int b = blockIdx.x, c = threadIdx.x;
    __shared__ float sy[NH * CDIM];
    __shared__ float pre[CDIM];
    for (int i = c; i < NH * CDIM; i += CDIM) sy[i] = g_y[b * NH * CDIM + i];
    __syncthreads();
    int h = c / 48;
    float a = bv[c];
    for (int j = 0; j < CDIM; j++) a += Wv[c * CDIM + j] * sy[h * CDIM + j];
    pre[c] = a;
    __syncthreads();
    float o = bo[c];
    for (int j = 0; j < CDIM; j++) o += Wo[c * CDIM + j] * pre[j];
    g_out[b * CDIM + c] = o;
}

// ------------------------------------------------------------- k7: broadcast
__global__ void k7_bcast(float* __restrict__ out) {
    int plane = blockIdx.x;
    int q = blockIdx.y;
    float v = g_out[plane];
    float4 vv = make_float4(v, v, v, v);
    float4* dst = (float4*)out + (size_t)plane * 16384 + q * 4096;
    #pragma unroll 4
    for (int i = threadIdx.x; i < 4096; i += 256) dst[i] = vv;
}

// ============================================================================
extern "C" void kernel_launch(void* const* d_in, const int* in_sizes, int n_in,
                              void* d_out, int out_size) {
    const float* Xf = (const float*)d_in[0];
    const float* Xs = (const float*)d_in[1];
    const float* Wq = (const float*)d_in[2];
    const float* bq = (const float*)d_in[3];
    const float* Wk = (const float*)d_in[4];
    // d_in[5] = bk: constant per (b,h) in scores, cancels in softmax
    const float* Wv = (const float*)d_in[6];
    const float* bv = (const float*)d_in[7];
    const float* Wo = (const float*)d_in[8];
    const float* bo = (const float*)d_in[9];

    k1_mean  <<<BATCH * CDIM, 512>>>(Xf);
    k2_proj  <<<BATCH, CDIM>>>(Wq, bq, Wk);
    k3_scores<<<BATCH * 128, 128>>>(Xs);
    k5_y     <<<dim3(16, 6, BATCH), 256>>>(Xs);
    k6_out   <<<BATCH, CDIM>>>(Wv, bv, Wo, bo);
    k7_bcast <<<dim3(BATCH * CDIM, 4), 256>>>((float*)d_out);
}

// round 4
// speedup vs baseline: 1.1324x; 1.1312x over previous
#include <cuda_runtime.h>
#include <cstdint>

// ============================================================================
// FrequencyToSpatialCrossAttention — collapsed; occupancy/pipeline edition.
//  k1: Qg = mean(X_f)                         read 402MB
//  k2: A[b,c,h] (scale folded), zero g_y      tiny
//  k3: scores+softmax, 1px/thread, 100% occ   read 402MB
//  k5: y accum, cp.async double-buffered      read 402MB
//  k6: (Wv@y+bv)@Wo^T+bo ; k7: broadcast      write 402MB
// ============================================================================

#define BATCH 4
#define CDIM  384
#define NH    8
#define NPIX  65536
#define NWIN  1024

typedef unsigned long long ull;

__device__ __forceinline__ ull pk(float x, float y) {
    ull r; asm("mov.b64 %0, {%1,%2};" : "=l"(r) : "f"(x), "f"(y)); return r;
}
__device__ __forceinline__ void upk(ull v, float& x, float& y) {
    asm("mov.b64 {%0,%1}, %2;" : "=f"(x), "=f"(y) : "l"(v));
}
__device__ __forceinline__ ull ffma2(ull a, ull b, ull c) {
    ull d; asm("fma.rn.f32x2 %0, %1, %2, %3;" : "=l"(d) : "l"(a), "l"(b), "l"(c));
    return d;
}
__device__ __forceinline__ uint32_t s2u(const void* p) {
    uint32_t a;
    asm("{ .reg .u64 t; cvta.to.shared.u64 t, %1; cvt.u32.u64 %0, t; }"
        : "=r"(a) : "l"(p));
    return a;
}
__device__ __forceinline__ void cpa16(uint32_t dst, const void* src) {
    asm volatile("cp.async.cg.shared.global [%0], [%1], 16;" :: "r"(dst), "l"(src));
}

__device__ float g_S  [BATCH*NH*NPIX];   // softmaxed weights, windowed layout
__device__ float g_Qg [BATCH*CDIM];
__device__ float g_A  [BATCH*CDIM*NH];   // [b][c][h], scale folded
__device__ float g_y  [BATCH*NH*CDIM];
__device__ float g_out[BATCH*CDIM];

// ---------------------------------------------------------------- k1: Qg mean
__global__ void k1_mean(const float* __restrict__ Xf) {
    int bc = blockIdx.x;
    const float4* src = (const float4*)Xf + (size_t)bc * 16384;
    float s0 = 0.f, s1 = 0.f;
    #pragma unroll 8
    for (int i = threadIdx.x; i < 16384; i += 1024) {
        float4 a = src[i], b = src[i + 512];
        s0 += (a.x + a.y) + (a.z + a.w);
        s1 += (b.x + b.y) + (b.z + b.w);
    }
    float s = s0 + s1;
    __shared__ float red[512];
    red[threadIdx.x] = s;
    __syncthreads();
    for (int o = 256; o > 0; o >>= 1) {
        if (threadIdx.x < o) red[threadIdx.x] += red[threadIdx.x + o];
        __syncthreads();
    }
    if (threadIdx.x == 0) g_Qg[bc] = red[0] * (1.f / 65536.f);
}

// ------------------------------------------------- k2: Q proj + A, zero g_y
__global__ void k2_proj(const float* __restrict__ Wq, const float* __restrict__ bq,
                        const float* __restrict__ Wk) {
    int b = blockIdx.x, c = threadIdx.x;
    __shared__ float qf[CDIM];
    const float* qg = &g_Qg[b * CDIM];
    float acc = bq[c];
    for (int j = 0; j < CDIM; j++) acc += qg[j] * Wq[c * CDIM + j];
    qf[c] = acc;
    __syncthreads();
    const float scale = 0.14433756729740643f;   // 48^-0.5
    #pragma unroll
    for (int h = 0; h < NH; h++) {
        float a = 0.f;
        for (int d = 0; d < 48; d++) a += qf[h * 48 + d] * Wk[(h * 48 + d) * CDIM + c];
        g_A[(b * CDIM + c) * NH + h] = a * scale;
    }
    for (int i = threadIdx.x; i < NH * CDIM; i += CDIM) g_y[b * NH * CDIM + i] = 0.f;
}

// ------------------------- k3: scores + softmax; strip = 8 rows x 32 cols
// 1 px per thread: full 384-c dot product in registers (packed head-pairs).
// Warp loads = 128B contiguous per c-iteration. 4 CTA/SM -> full occupancy.
__global__ void __launch_bounds__(256, 4) k3_scores(const float* __restrict__ Xs) {
    int bx   = blockIdx.x;              // 1024 = 4b * 256 strips
    int b    = bx >> 8;
    int sidx = bx & 255;
    int sr   = sidx >> 3;               // window row 0..31
    int scol = sidx & 7;                // 32-col strip 0..7
    int t = threadIdx.x;
    int r = t >> 5, col = t & 31;

    __shared__ float sA[CDIM * 8];      // 12KB raw [c][h]
    __shared__ float sS[8 * 264];       // scores [h][256] pitch 264

    for (int i = t; i < CDIM * 8; i += 256) sA[i] = g_A[b * CDIM * 8 + i];
    __syncthreads();

    int ii = sr * 8 + r;
    int jj = scol * 32 + col;
    int si = (ii + 252) & 255;          // rolled source coords
    int sj = (jj + 252) & 255;
    const float* xp = Xs + (size_t)b * CDIM * NPIX + si * 256 + sj;

    ull acc[4];
    #pragma unroll
    for (int q = 0; q < 4; q++) acc[q] = pk(0.f, 0.f);

    const ulonglong2* sA2 = (const ulonglong2*)sA;
    #pragma unroll 8
    for (int c = 0; c < CDIM; c++) {
        float x = xp[(size_t)c << 16];
        ull x2 = pk(x, x);
        ulonglong2 a01 = sA2[c * 2];
        ulonglong2 a23 = sA2[c * 2 + 1];
        acc[0] = ffma2(x2, a01.x, acc[0]);
        acc[1] = ffma2(x2, a01.y, acc[1]);
        acc[2] = ffma2(x2, a23.x, acc[2]);
        acc[3] = ffma2(x2, a23.y, acc[3]);
    }

    int p = r * 32 + col;
    #pragma unroll
    for (int q = 0; q < 4; q++) {
        float lo, hi; upk(acc[q], lo, hi);
        sS[(2 * q) * 264 + p]     = lo;
        sS[(2 * q + 1) * 264 + p] = hi;
    }
    __syncthreads();

    // softmax: 32 (h,win) groups, 2 threads each (sub = rows 0-3 / 4-7)
    if (t < 64) {
        int pair = t >> 1, sub = t & 1;
        int h = pair >> 2, win = pair & 3;
        int base = h * 264 + win * 8;
        float4 v[8];
        #pragma unroll
        for (int rr = 0; rr < 4; rr++) {
            int off = base + (sub * 4 + rr) * 32;
            v[rr * 2]     = *(const float4*)&sS[off];
            v[rr * 2 + 1] = *(const float4*)&sS[off + 4];
        }
        float m = -1e30f;
        #pragma unroll
        for (int q = 0; q < 8; q++)
            m = fmaxf(m, fmaxf(fmaxf(v[q].x, v[q].y), fmaxf(v[q].z, v[q].w)));
        m = fmaxf(m, __shfl_xor_sync(0xffffffffu, m, 1));
        float Z = 0.f;
        #pragma unroll
        for (int q = 0; q < 8; q++) {
            v[q].x = __expf(v[q].x - m); v[q].y = __expf(v[q].y - m);
            v[q].z = __expf(v[q].z - m); v[q].w = __expf(v[q].w - m);
            Z += (v[q].x + v[q].y) + (v[q].z + v[q].w);
        }
        Z += __shfl_xor_sync(0xffffffffu, Z, 1);
        float inv = 1.f / (Z * 1024.f);             // fold 1/nW

        int gwin = sr * 32 + scol * 4 + win;
        size_t gbase = ((size_t)(b * 8 + h) * NWIN + gwin) * 64;
        #pragma unroll
        for (int rr = 0; rr < 4; rr++) {
            int rloc = (sub * 4 + rr) * 8;
            float4 e0 = v[rr * 2], e1 = v[rr * 2 + 1];
            e0.x *= inv; e0.y *= inv; e0.z *= inv; e0.w *= inv;
            e1.x *= inv; e1.y *= inv; e1.z *= inv; e1.w *= inv;
            *(float4*)&g_S[gbase + rloc]     = e0;
            *(float4*)&g_S[gbase + rloc + 4] = e1;
        }
    }
}

// ---------------------------------------------------------------- k5: y accum
// cp.async double-buffered; tile = 64ch x 64px; pitch 68 floats (17 x 16B).
// grid = 288 (4b x 6 cchunk x 12 slices) = one full wave at 2 CTA/SM.
__global__ void __launch_bounds__(256) k5_y(const float* __restrict__ Xs) {
    int unit = blockIdx.x;
    int b = unit / 72;
    int rem = unit % 72;
    int cchunk = rem / 12;
    int s = rem % 12;
    int cc0 = cchunk * 64;
    int t0 = (s * 1024) / 12, t1 = ((s + 1) * 1024) / 12;   // 64-px tiles

    __shared__ float xt[2][64 * 68];    // 2 x 17KB
    __shared__ float wt[2][8 * 68];     // 2 x 2.2KB

    int tid = threadIdx.x;
    int cg = tid & 15, tg = tid >> 4;
    int lane = tid & 31, wid = tid >> 5;

    const float4* xsp0 = (const float4*)Xs + (size_t)(b * CDIM + cc0) * 16384;
    uint32_t xt_u[2] = { s2u(&xt[0][0]), s2u(&xt[1][0]) };
    uint32_t wt_u[2] = { s2u(&wt[0][0]), s2u(&wt[1][0]) };

    ull acc[4][8];
    #pragma unroll
    for (int i = 0; i < 4; i++)
        #pragma unroll
        for (int h = 0; h < 8; h++) acc[i][h] = pk(0.f, 0.f);

    // stage tile -> buf
    auto stage = [&](int tile, int buf) {
        // x: 64ch x 16 float4 = 1024 chunks; 4 per thread
        #pragma unroll
        for (int j = 0; j < 4; j++) {
            int i = tid + j * 256;
            int c = i >> 4, tf4 = i & 15;
            cpa16(xt_u[buf] + (c * 68 + tf4 * 4) * 4,
                  xsp0 + (size_t)c * 16384 + tile * 16 + tf4);
        }
        // w: 8h x 16 float4 = 128 chunks; threads 0..127
        if (tid < 128) {
            int h = tid >> 4, tf4 = tid & 15;
            int p = tile * 64 + tf4 * 4;
            int sy = p >> 8, sx = p & 255;
            int iy = (sy + 4) & 255, ix = (sx + 4) & 255;
            size_t idx = ((size_t)(b * 8 + h) * NWIN + (iy >> 3) * 32 + (ix >> 3)) * 64
                         + (iy & 7) * 8 + (ix & 7);
            cpa16(wt_u[buf] + (h * 68 + tf4 * 4) * 4, &g_S[idx]);
        }
    };

    int nt = t1 - t0;
    stage(t0, 0);
    asm volatile("cp.async.commit_group;");

    int t4 = tg * 4;
    for (int k = 0; k < nt; k++) {
        asm volatile("cp.async.wait_group 0;" ::: "memory");
        __syncthreads();
        if (k + 1 < nt) {
            stage(t0 + k + 1, (k + 1) & 1);
            asm volatile("cp.async.commit_group;");
        }
        int buf = k & 1;
        const float* xb = xt[buf];
        const float* wb = wt[buf];
        ull wlo[8], whi[8];
        #pragma unroll
        for (int h = 0; h < 8; h++) {
            float4 wv = *(const float4*)&wb[h * 68 + t4];
            wlo[h] = pk(wv.x, wv.y); whi[h] = pk(wv.z, wv.w);
        }
        #pragma unroll
        for (int i = 0; i < 4; i++) {
            float4 xv = *(const float4*)&xb[(cg + i * 16) * 68 + t4];
            ull xlo = pk(xv.x, xv.y), xhi = pk(xv.z, xv.w);
            #pragma unroll
            for (int h = 0; h < 8; h++) {
                acc[i][h] = ffma2(xlo, wlo[h], acc[i][h]);
                acc[i][h] = ffma2(xhi, whi[h], acc[i][h]);
            }
        }
    }
    __syncthreads();

    // fold: packed halves + tg-pair shfl; per-warp partials in xt[0]; one
    // atomicAdd per (h,c) per block.
    float* sred = &xt[0][0];
    #pragma unroll
    for (int i = 0; i < 4; i++)
        #pragma unroll
        for (int h = 0; h < 8; h++) {
            float lo, hi; upk(acc[i][h], lo, hi);
            float vsum = lo + hi;
            vsum += __shfl_xor_sync(0xffffffffu, vsum, 16);
            if (lane < 16) sred[wid * 512 + i * 128 + h * 16 + lane] = vsum;
        }
    __syncthreads();
    #pragma unroll
    for (int o = tid; o < 512; o += 256) {
        float sm = 0.f;
        #pragma unroll
        for (int w = 0; w < 8; w++) sm += sred[w * 512 + o];
        int i = o >> 7, h = (o >> 4) & 7, c = cc0 + (o & 15) + 16 * i;
        atomicAdd(&g_y[b * NH * CDIM + h * CDIM + c], sm);
    }
}

// ----------------------------------------------------------- k6: tiny finals
__global__ void k6_out(const float* __restrict__ Wv, const float* __restrict__ bv,
                       const float* __restrict__ Wo, const float* __restrict__ bo) {
    int b = blockIdx.x, c = threadIdx.x;
    __shared__ float sy[NH * CDIM];
    __shared__ float pre[CDIM];
    for (int i = c; i < NH * CDIM; i += CDIM) sy[i] = g_y[b * NH * CDIM + i];
    __syncthreads();
    int h = c / 48;
    float a = bv[c];
    for (int j = 0; j < CDIM; j++) a += Wv[c * CDIM + j] * sy[h * CDIM + j];
    pre[c] = a;
    __syncthreads();
    float o = bo[c];
    for (int j = 0; j < CDIM; j++) o += Wo[c * CDIM + j] * pre[j];
    g_out[b * CDIM + c] = o;
}

// ------------------------------------------------------------- k7: broadcast
__global__ void k7_bcast(float* __restrict__ out) {
    int plane = blockIdx.x;
    int q = blockIdx.y;
    float v = g_out[plane];
    float4 vv = make_float4(v, v, v, v);
    float4* dst = (float4*)out + (size_t)plane * 16384 + q * 4096;
    #pragma unroll 4
    for (int i = threadIdx.x; i < 4096; i += 256) dst[i] = vv;
}

// ============================================================================
extern "C" void kernel_launch(void* const* d_in, const int* in_sizes, int n_in,
                              void* d_out, int out_size) {
    const float* Xf = (const float*)d_in[0];
    const float* Xs = (const float*)d_in[1];
    const float* Wq = (const float*)d_in[2];
    const float* bq = (const float*)d_in[3];
    const float* Wk = (const float*)d_in[4];
    // d_in[5] = bk: constant per (b,h) in scores, cancels in softmax
    const float* Wv = (const float*)d_in[6];
    const float* bv = (const float*)d_in[7];
    const float* Wo = (const float*)d_in[8];
    const float* bo = (const float*)d_in[9];

    k1_mean  <<<BATCH * CDIM, 512>>>(Xf);
    k2_proj  <<<BATCH, CDIM>>>(Wq, bq, Wk);
    k3_scores<<<BATCH * 256, 256>>>(Xs);
    k5_y     <<<288, 256>>>(Xs);
    k6_out   <<<BATCH, CDIM>>>(Wv, bv, Wo, bo);
    k7_bcast <<<dim3(BATCH * CDIM, 4), 256>>>((float*)d_out);
}